// round 1
// baseline (speedup 1.0000x reference)
#include <cuda_runtime.h>
#include <math.h>

// Problem constants
#define BATCH 8192
#define PLANE (8192 * 128)          // per-component plane stride (max M = 128)
#define GAIN 1.5927116870880127f
#define INV_SQRT3 0.57735026918962576f

// ---------------------------------------------------------------------------
// Scratch (device globals; no allocation in kernel_launch)
// ---------------------------------------------------------------------------
__device__ float g_s [PLANE];
__device__ float g_v [3 * PLANE];
__device__ float g_s1[PLANE];
__device__ float g_v1[3 * PLANE];
__device__ float g_s2[PLANE];
__device__ float g_v2[3 * PLANE];
__device__ float g_ts[PLANE];
__device__ float g_tv[3 * PLANE];

// ---------------------------------------------------------------------------
// split: x (B,256) -> s (B,64), v planes (B,64) x3   [x v-layout interleaved]
// ---------------------------------------------------------------------------
__global__ void split_kernel(const float* __restrict__ x,
                             float* __restrict__ s, float* __restrict__ v) {
    int i = blockIdx.x * 256 + threadIdx.x;      // over B*64
    if (i >= BATCH * 64) return;
    int b = i >> 6, u = i & 63;
    const float* xr = x + b * 256;
    s[i] = xr[u];
    v[0 * PLANE + i] = xr[64 + 3 * u + 0];
    v[1 * PLANE + i] = xr[64 + 3 * u + 1];
    v[2 * PLANE + i] = xr[64 + 3 * u + 2];
}

// ---------------------------------------------------------------------------
// pack: final s (B,64), v planes (B,64) -> out (B,256) interleaved
// ---------------------------------------------------------------------------
__global__ void pack_kernel(const float* __restrict__ s,
                            const float* __restrict__ v,
                            float* __restrict__ out) {
    int i = blockIdx.x * 256 + threadIdx.x;      // over B*64
    if (i >= BATCH * 64) return;
    int b = i >> 6, u = i & 63;
    float* orow = out + b * 256;
    orow[u] = s[i];
    orow[64 + 3 * u + 0] = v[0 * PLANE + i];
    orow[64 + 3 * u + 1] = v[1 * PLANE + i];
    orow[64 + 3 * u + 2] = v[2 * PLANE + i];
}

// ---------------------------------------------------------------------------
// Generic small GEMM: Y[b,n] = scale * sum_k X[b,k] * W[k,n]
// blockDim (32,8). CTA = 64 rows x N cols. NC = cols per thread (N = 32*NC).
// K in {64,128}, multiple of 32. B multiple of 64.
// ---------------------------------------------------------------------------
template <int NC>
__global__ __launch_bounds__(256)
void gemm_kernel(const float* __restrict__ X, const float* __restrict__ Wm,
                 float* __restrict__ Y, int K, float scale) {
    constexpr int N = 32 * NC;
    __shared__ float Xs[64][33];
    __shared__ float Ws[32][N + 1];
    const int tx = threadIdx.x, ty = threadIdx.y;
    const int tid = ty * 32 + tx;
    const int row0 = blockIdx.x * 64;

    float acc[8][NC];
#pragma unroll
    for (int r = 0; r < 8; ++r)
#pragma unroll
        for (int j = 0; j < NC; ++j) acc[r][j] = 0.f;

    for (int k0 = 0; k0 < K; k0 += 32) {
#pragma unroll
        for (int e = tid; e < 64 * 32; e += 256) {
            int r = e >> 5, kk = e & 31;
            Xs[r][kk] = X[(row0 + r) * K + k0 + kk];
        }
        for (int e = tid; e < 32 * N; e += 256) {
            int kk = e / N, n = e - kk * N;
            Ws[kk][n] = Wm[(k0 + kk) * N + n];
        }
        __syncthreads();
#pragma unroll 8
        for (int kk = 0; kk < 32; ++kk) {
            float wv[NC];
#pragma unroll
            for (int j = 0; j < NC; ++j) wv[j] = Ws[kk][tx * NC + j];
#pragma unroll
            for (int r = 0; r < 8; ++r) {
                float xv = Xs[ty * 8 + r][kk];
#pragma unroll
                for (int j = 0; j < NC; ++j) acc[r][j] += xv * wv[j];
            }
        }
        __syncthreads();
    }
#pragma unroll
    for (int r = 0; r < 8; ++r)
#pragma unroll
        for (int j = 0; j < NC; ++j)
            Y[(row0 + ty * 8 + r) * N + tx * NC + j] = scale * acc[r][j];
}

// ---------------------------------------------------------------------------
// Tensor product (the heavy stage).
//   ts[b,w]    = c * ( sum_{u,v} s1 s2 wss  + (1/sqrt3) sum_{u,v,i} v1_i v2_i wvv )
//   tv_i[b,w]  = c * ( sum_{u,v} s1 v2_i wsv + v1_i s2 wvs )
// W (output dim) = 128 always. Weights layout [u][v][w] row-major.
// CTA: TB=16 samples x all 128 w. threads (32,8): tx -> 4 consecutive w,
// ty -> 2 samples. Inner loop over (u, v) with float4 weight loads.
// ---------------------------------------------------------------------------
template <int M>
__global__ __launch_bounds__(256)
void tp_kernel(const float* __restrict__ s1, const float* __restrict__ v1,
               const float* __restrict__ s2, const float* __restrict__ v2,
               const float* __restrict__ wss, const float* __restrict__ wvv,
               const float* __restrict__ wsv, const float* __restrict__ wvs,
               float* __restrict__ ts, float* __restrict__ tv, float c) {
    constexpr int TB = 16, UC = 32, W = 128;
    __shared__ float s2t[TB][M];
    __shared__ float v2t[3][TB][M];
    __shared__ float s1c[TB][UC];
    __shared__ float v1c[3][TB][UC];

    const int tx = threadIdx.x, ty = threadIdx.y;
    const int tid = ty * 32 + tx;
    const int b0 = blockIdx.x * TB;

    // resident tiles of the "right" operands
    for (int e = tid; e < TB * M; e += 256) {
        int b = e / M, vv = e % M;
        int gi = (b0 + b) * M + vv;
        s2t[b][vv]    = s2[gi];
        v2t[0][b][vv] = v2[0 * PLANE + gi];
        v2t[1][b][vv] = v2[1 * PLANE + gi];
        v2t[2][b][vv] = v2[2 * PLANE + gi];
    }

    const int bl0 = ty * 2, bl1 = ty * 2 + 1;
    const int w0 = tx * 4;

    float accS[2][4];
    float accV[2][3][4];
#pragma unroll
    for (int sS = 0; sS < 2; ++sS) {
#pragma unroll
        for (int j = 0; j < 4; ++j) accS[sS][j] = 0.f;
#pragma unroll
        for (int i = 0; i < 3; ++i)
#pragma unroll
            for (int j = 0; j < 4; ++j) accV[sS][i][j] = 0.f;
    }

    for (int uc = 0; uc < M; uc += UC) {
        __syncthreads();
        for (int e = tid; e < TB * UC; e += 256) {
            int b = e / UC, uu = e % UC;
            int gi = (b0 + b) * M + uc + uu;
            s1c[b][uu]    = s1[gi];
            v1c[0][b][uu] = v1[0 * PLANE + gi];
            v1c[1][b][uu] = v1[1 * PLANE + gi];
            v1c[2][b][uu] = v1[2 * PLANE + gi];
        }
        __syncthreads();

        for (int uu = 0; uu < UC; ++uu) {
            const int u = uc + uu;
            const float as0 = s1c[bl0][uu];
            const float as1 = s1c[bl1][uu];
            const float a00 = v1c[0][bl0][uu], a01 = v1c[1][bl0][uu], a02 = v1c[2][bl0][uu];
            const float a10 = v1c[0][bl1][uu], a11 = v1c[1][bl1][uu], a12 = v1c[2][bl1][uu];
            const int base = (u * M) * W + w0;

#pragma unroll 2
            for (int vv = 0; vv < M; ++vv) {
                const int wi = base + vv * W;
                float4 t;
                float wS[4], wV[4], wSV[4], wVS[4];
                t = *(const float4*)(wss + wi); wS[0]=t.x; wS[1]=t.y; wS[2]=t.z; wS[3]=t.w;
                t = *(const float4*)(wvv + wi); wV[0]=t.x; wV[1]=t.y; wV[2]=t.z; wV[3]=t.w;
                t = *(const float4*)(wsv + wi); wSV[0]=t.x; wSV[1]=t.y; wSV[2]=t.z; wSV[3]=t.w;
                t = *(const float4*)(wvs + wi); wVS[0]=t.x; wVS[1]=t.y; wVS[2]=t.z; wVS[3]=t.w;

                // sample 0
                {
                    const float bs  = s2t[bl0][vv];
                    const float bv0 = v2t[0][bl0][vv], bv1 = v2t[1][bl0][vv], bv2 = v2t[2][bl0][vv];
                    const float pss = as0 * bs;
                    const float pvv = (a00 * bv0 + a01 * bv1 + a02 * bv2) * INV_SQRT3;
#pragma unroll
                    for (int j = 0; j < 4; ++j) accS[0][j] += pss * wS[j] + pvv * wV[j];
                    const float psv[3] = {as0 * bv0, as0 * bv1, as0 * bv2};
                    const float pvs[3] = {a00 * bs, a01 * bs, a02 * bs};
#pragma unroll
                    for (int i = 0; i < 3; ++i)
#pragma unroll
                        for (int j = 0; j < 4; ++j)
                            accV[0][i][j] += psv[i] * wSV[j] + pvs[i] * wVS[j];
                }
                // sample 1
                {
                    const float bs  = s2t[bl1][vv];
                    const float bv0 = v2t[0][bl1][vv], bv1 = v2t[1][bl1][vv], bv2 = v2t[2][bl1][vv];
                    const float pss = as1 * bs;
                    const float pvv = (a10 * bv0 + a11 * bv1 + a12 * bv2) * INV_SQRT3;
#pragma unroll
                    for (int j = 0; j < 4; ++j) accS[1][j] += pss * wS[j] + pvv * wV[j];
                    const float psv[3] = {as1 * bv0, as1 * bv1, as1 * bv2};
                    const float pvs[3] = {a10 * bs, a11 * bs, a12 * bs};
#pragma unroll
                    for (int i = 0; i < 3; ++i)
#pragma unroll
                        for (int j = 0; j < 4; ++j)
                            accV[1][i][j] += psv[i] * wSV[j] + pvs[i] * wVS[j];
                }
            }
        }
    }

    const int bg[2] = {b0 + bl0, b0 + bl1};
#pragma unroll
    for (int sS = 0; sS < 2; ++sS) {
        const int orow = bg[sS] * W + w0;
#pragma unroll
        for (int j = 0; j < 4; ++j) ts[orow + j] = c * accS[sS][j];
#pragma unroll
        for (int i = 0; i < 3; ++i)
#pragma unroll
            for (int j = 0; j < 4; ++j)
                tv[i * PLANE + orow + j] = c * accV[sS][i][j];
    }
}

// ---------------------------------------------------------------------------
// gate combine: gs = G*tanh(sl); gv_i = G*tanh(g) * vl_i   (all B x 128)
// ---------------------------------------------------------------------------
__global__ void gate_kernel(const float* __restrict__ sl, const float* __restrict__ g,
                            const float* __restrict__ vl,
                            float* __restrict__ gs, float* __restrict__ gv) {
    int i = blockIdx.x * 256 + threadIdx.x;      // over B*128
    if (i >= BATCH * 128) return;
    gs[i] = GAIN * tanhf(sl[i]);
    float t = GAIN * tanhf(g[i]);
    gv[0 * PLANE + i] = t * vl[0 * PLANE + i];
    gv[1 * PLANE + i] = t * vl[1 * PLANE + i];
    gv[2 * PLANE + i] = t * vl[2 * PLANE + i];
}

// ---------------------------------------------------------------------------
// Host orchestration
// ---------------------------------------------------------------------------
static inline void run_gemm(const float* X, const float* W, float* Y,
                            int K, int N, float scale) {
    dim3 blk(32, 8), grd(BATCH / 64);
    if (N == 64) gemm_kernel<2><<<grd, blk>>>(X, W, Y, K, scale);
    else         gemm_kernel<4><<<grd, blk>>>(X, W, Y, K, scale);
}

extern "C" void kernel_launch(void* const* d_in, const int* in_sizes, int n_in,
                              void* d_out, int out_size) {
    const float* in[29];
    for (int i = 0; i < 29; ++i) in[i] = (const float*)d_in[i];
    float* out = (float*)d_out;

    float *s, *v, *s1, *v1, *s2, *v2, *ts, *tv;
    cudaGetSymbolAddress((void**)&s,  g_s);
    cudaGetSymbolAddress((void**)&v,  g_v);
    cudaGetSymbolAddress((void**)&s1, g_s1);
    cudaGetSymbolAddress((void**)&v1, g_v1);
    cudaGetSymbolAddress((void**)&s2, g_s2);
    cudaGetSymbolAddress((void**)&v2, g_v2);
    cudaGetSymbolAddress((void**)&ts, g_ts);
    cudaGetSymbolAddress((void**)&tv, g_tv);

    const float c64  = 0.125f;                      // 1/sqrt(64)
    const float c128 = 0.08838834764831845f;        // 1/sqrt(128)
    const float ctp1 = 1.0f / (64.0f  * 1.4142135623730951f);
    const float ctp2 = 1.0f / (128.0f * 1.4142135623730951f);

    dim3 tpb(32, 8);

    split_kernel<<<BATCH * 64 / 256, 256>>>(in[0], s, v);

    // ---------------- block 1 (m = 64) ----------------
    run_gemm(s, in[1], s1, 64, 64, c64);
    for (int i = 0; i < 3; ++i) run_gemm(v + i * PLANE, in[2], v1 + i * PLANE, 64, 64, c64);
    run_gemm(s, in[3], s2, 64, 64, c64);
    for (int i = 0; i < 3; ++i) run_gemm(v + i * PLANE, in[4], v2 + i * PLANE, 64, 64, c64);

    tp_kernel<64><<<BATCH / 16, tpb>>>(s1, v1, s2, v2, in[5], in[6], in[7], in[8], ts, tv, ctp1);

    run_gemm(ts, in[9],  s1, 128, 128, c128);   // sl
    run_gemm(ts, in[10], s2, 128, 128, c128);   // g
    for (int i = 0; i < 3; ++i) run_gemm(tv + i * PLANE, in[11], v1 + i * PLANE, 128, 128, c128);
    gate_kernel<<<BATCH * 128 / 256, 256>>>(s1, s2, v1, ts, tv);   // gs->ts, gv->tv

    run_gemm(ts, in[12], s, 128, 128, c128);
    for (int i = 0; i < 3; ++i) run_gemm(tv + i * PLANE, in[13], v + i * PLANE, 128, 128, c128);

    // ---------------- block 2 (m = 128) ----------------
    run_gemm(s, in[14], s1, 128, 128, c128);
    for (int i = 0; i < 3; ++i) run_gemm(v + i * PLANE, in[15], v1 + i * PLANE, 128, 128, c128);
    run_gemm(s, in[16], s2, 128, 128, c128);
    for (int i = 0; i < 3; ++i) run_gemm(v + i * PLANE, in[17], v2 + i * PLANE, 128, 128, c128);

    tp_kernel<128><<<BATCH / 16, tpb>>>(s1, v1, s2, v2, in[18], in[19], in[20], in[21], ts, tv, ctp2);

    run_gemm(ts, in[22], s1, 128, 128, c128);   // sl
    run_gemm(ts, in[23], s2, 128, 128, c128);   // g
    for (int i = 0; i < 3; ++i) run_gemm(tv + i * PLANE, in[24], v1 + i * PLANE, 128, 128, c128);
    gate_kernel<<<BATCH * 128 / 256, 256>>>(s1, s2, v1, ts, tv);

    run_gemm(ts, in[25], s, 128, 128, c128);
    for (int i = 0; i < 3; ++i) run_gemm(tv + i * PLANE, in[26], v + i * PLANE, 128, 128, c128);

    // ---------------- final linear + pack ----------------
    run_gemm(s, in[27], s1, 128, 64, c128);
    for (int i = 0; i < 3; ++i) run_gemm(v + i * PLANE, in[28], v1 + i * PLANE, 128, 64, c128);

    pack_kernel<<<BATCH * 64 / 256, 256>>>(s1, v1, out);
}

// round 4
// speedup vs baseline: 3.9265x; 3.9265x over previous
#include <cuda_runtime.h>
#include <cstdint>
#include <math.h>

#define BATCH 8192
#define PLANE (8192 * 128)
#define GAIN 1.5927116870880127f
#define INV_SQRT3 0.57735026918962576f

// ---------------------------------------------------------------------------
// Scratch (device globals; no allocation in kernel_launch)
// ---------------------------------------------------------------------------
__device__ float g_s [PLANE];
__device__ float g_v [3 * PLANE];
__device__ float g_s1[PLANE];
__device__ float g_v1[3 * PLANE];
__device__ float g_s2[PLANE];
__device__ float g_v2[3 * PLANE];
__device__ float g_ts[PLANE];
__device__ float g_tv[3 * PLANE];

// ---------------------------------------------------------------------------
// helpers (non-arch-gated PTX only: mma.sync bf16 m16n8k16, sm_80+)
// ---------------------------------------------------------------------------
#define MMA_BF16(d, a0, a1, a2, a3, b0, b1)                                 \
    asm volatile(                                                           \
        "mma.sync.aligned.m16n8k16.row.col.f32.bf16.bf16.f32 "              \
        "{%0,%1,%2,%3}, {%4,%5,%6,%7}, {%8,%9}, {%0,%1,%2,%3};"             \
        : "+f"((d)[0]), "+f"((d)[1]), "+f"((d)[2]), "+f"((d)[3])            \
        : "r"(a0), "r"(a1), "r"(a2), "r"(a3), "r"(b0), "r"(b1))

// split x0,x1 into packed bf16 hi-word and lo-word (low half = x0)
__device__ __forceinline__ void split_pack(float x0, float x1,
                                           uint32_t& hi, uint32_t& lo) {
    uint32_t h;
    asm("cvt.rn.bf16x2.f32 %0, %1, %2;" : "=r"(h) : "f"(x1), "f"(x0));
    float h0 = __uint_as_float(h << 16);
    float h1 = __uint_as_float(h & 0xFFFF0000u);
    float l0 = x0 - h0;
    float l1 = x1 - h1;
    asm("cvt.rn.bf16x2.f32 %0, %1, %2;" : "=r"(lo) : "f"(l1), "f"(l0));
    hi = h;
}

// ---------------------------------------------------------------------------
// Tensor product via bf16x3 mma.sync (error-compensated).
//   ds[b,w]   = c*( sum_{uv} s1s2 Wss + inv_sqrt3 * sum_{uv} (v1.v2) Wvv )
//   dv_i[b,w] = c*( sum_{uv} s1 v2_i Wsv + v1_i s2 Wvs )
// CTA: 64 batch rows x 128 w x 4 outputs; 16 warps = 4 outs x 4 row-quads.
// k-window = 16 v-cols; u inner loop; weights double-buffered bf16 hi/lo
// planes in smem (8 planes x [8 kp][136] words); a2 operands in smem.
// ---------------------------------------------------------------------------
template <int M>
__global__ __launch_bounds__(512, 1)
void tp_mma_kernel(const float* __restrict__ s1, const float* __restrict__ v1,
                   const float* __restrict__ s2, const float* __restrict__ v2,
                   const float* __restrict__ wss, const float* __restrict__ wvv,
                   const float* __restrict__ wsv, const float* __restrict__ wvs,
                   float* __restrict__ ts, float* __restrict__ tv, float cscale) {
    extern __shared__ uint32_t dsm[];
    uint32_t* bufw = dsm;                          // [2][8 pl][8 kp][136]
    float* a2s = (float*)(dsm + 2 * 8 * 8 * 136);  // [4][64][17]

    const int tid  = threadIdx.x;
    const int wid  = tid >> 5, lane = tid & 31;
    const int out  = wid & 3;
    const int q    = wid >> 2;
    const int g    = lane >> 2, t4 = lane & 3;
    const int bb   = blockIdx.x * 64;
    const int lr0  = q * 16 + g, lr1 = lr0 + 8;
    const int gb0  = bb + lr0,   gb1 = bb + lr1;

    // copy role
    const int cp   = tid >> 7;            // weight plane 0..3
    const int rem  = tid & 127;
    const int kp   = rem >> 4;            // k-pair row 0..7
    const int n0   = (rem & 15) * 8;      // n segment
    const float* wp = (cp == 0) ? wss : (cp == 1) ? wvv : (cp == 2) ? wsv : wvs;

    const int pa_hi = (out == 0) ? 0 : 4;
    const int pb_hi = (out == 0) ? 2 : 6;

    float acc[16][4];
#pragma unroll
    for (int nt = 0; nt < 16; ++nt)
#pragma unroll
        for (int j = 0; j < 4; ++j) acc[nt][j] = 0.f;

    float wr[16];   // weight prefetch regs (2 rows x 8 n)

    auto ldw = [&](int u, int v0w) {
        const float* src = wp + ((size_t)u * M + v0w + 2 * kp) * 128 + n0;
        float4 a = *(const float4*)(src);
        float4 b = *(const float4*)(src + 4);
        float4 c = *(const float4*)(src + 128);
        float4 d = *(const float4*)(src + 132);
        wr[0]=a.x; wr[1]=a.y; wr[2]=a.z;  wr[3]=a.w;
        wr[4]=b.x; wr[5]=b.y; wr[6]=b.z;  wr[7]=b.w;
        wr[8]=c.x; wr[9]=c.y; wr[10]=c.z; wr[11]=c.w;
        wr[12]=d.x; wr[13]=d.y; wr[14]=d.z; wr[15]=d.w;
    };
    auto stw = [&](int buf) {
        uint32_t hw[8], lw[8];
#pragma unroll
        for (int j = 0; j < 8; ++j) split_pack(wr[j], wr[8 + j], hw[j], lw[j]);
        uint32_t* ph = bufw + ((size_t)(buf * 8 + 2 * cp) * 8 + kp) * 136 + n0;
        uint32_t* pl = bufw + ((size_t)(buf * 8 + 2 * cp + 1) * 8 + kp) * 136 + n0;
        *(uint4*)(ph)     = make_uint4(hw[0], hw[1], hw[2], hw[3]);
        *(uint4*)(ph + 4) = make_uint4(hw[4], hw[5], hw[6], hw[7]);
        *(uint4*)(pl)     = make_uint4(lw[0], lw[1], lw[2], lw[3]);
        *(uint4*)(pl + 4) = make_uint4(lw[4], lw[5], lw[6], lw[7]);
    };

    for (int v0w = 0; v0w < M; v0w += 16) {
        __syncthreads();   // previous window consumers done (a2s + buf)

        // fill a2 operand cache: [4 planes][64 rows][17]
        {
            const int f  = tid * 8;
            const int pp = f >> 10, lr = (f >> 4) & 63, j0 = f & 15;
            const float* src = (pp == 0) ? s2 : v2 + (size_t)(pp - 1) * PLANE;
            float4 a = *(const float4*)(src + (size_t)(bb + lr) * M + v0w + j0);
            float4 b = *(const float4*)(src + (size_t)(bb + lr) * M + v0w + j0 + 4);
            float* dst = a2s + pp * 1088 + lr * 17 + j0;
            dst[0]=a.x; dst[1]=a.y; dst[2]=a.z; dst[3]=a.w;
            dst[4]=b.x; dst[5]=b.y; dst[6]=b.z; dst[7]=b.w;
        }

        ldw(0, v0w);
        stw(0);
        ldw(1, v0w);

        for (int u = 0; u < M; ++u) {
            __syncthreads();   // buf[u&1] + a2s visible
            const int cur = u & 1;

            // ---- a1 operands (gmem, L1-hot) ----
            float s1a[2], v1a[3][2];
            s1a[0] = s1[(size_t)gb0 * M + u];
            s1a[1] = s1[(size_t)gb1 * M + u];
#pragma unroll
            for (int i = 0; i < 3; ++i) {
                v1a[i][0] = v1[(size_t)i * PLANE + (size_t)gb0 * M + u];
                v1a[i][1] = v1[(size_t)i * PLANE + (size_t)gb1 * M + u];
            }

            // ---- a2 operands from smem ----
            float s2v[2][4], v2v[3][2][4];
#pragma unroll
            for (int r = 0; r < 2; ++r) {
                const int lr = (r == 0) ? lr0 : lr1;
#pragma unroll
                for (int j = 0; j < 4; ++j) {
                    const int c = 2 * t4 + (j & 1) + 8 * (j >> 1);
                    s2v[r][j] = a2s[lr * 17 + c];
                    v2v[0][r][j] = a2s[1088 + lr * 17 + c];
                    v2v[1][r][j] = a2s[2176 + lr * 17 + c];
                    v2v[2][r][j] = a2s[3264 + lr * 17 + c];
                }
            }

            // ---- products + bf16 split fragments ----
            float pav[2][4], pbv[2][4];
            if (out == 0) {
#pragma unroll
                for (int r = 0; r < 2; ++r)
#pragma unroll
                    for (int j = 0; j < 4; ++j) {
                        pav[r][j] = s1a[r] * s2v[r][j];
                        pbv[r][j] = INV_SQRT3 * (v1a[0][r] * v2v[0][r][j] +
                                                 v1a[1][r] * v2v[1][r][j] +
                                                 v1a[2][r] * v2v[2][r][j]);
                    }
            } else {
                const int i = out - 1;
#pragma unroll
                for (int r = 0; r < 2; ++r)
#pragma unroll
                    for (int j = 0; j < 4; ++j) {
                        pav[r][j] = s1a[r] * v2v[i][r][j];
                        pbv[r][j] = v1a[i][r] * s2v[r][j];
                    }
            }
            uint32_t fah[4], fal[4], fbh[4], fbl[4];
            split_pack(pav[0][0], pav[0][1], fah[0], fal[0]);
            split_pack(pav[1][0], pav[1][1], fah[1], fal[1]);
            split_pack(pav[0][2], pav[0][3], fah[2], fal[2]);
            split_pack(pav[1][2], pav[1][3], fah[3], fal[3]);
            split_pack(pbv[0][0], pbv[0][1], fbh[0], fbl[0]);
            split_pack(pbv[1][0], pbv[1][1], fbh[1], fbl[1]);
            split_pack(pbv[0][2], pbv[0][3], fbh[2], fbl[2]);
            split_pack(pbv[1][2], pbv[1][3], fbh[3], fbl[3]);

            // ---- MMAs: hi*hi + lo*hi + hi*lo per stream ----
            const uint32_t* bah = bufw + ((size_t)(cur * 8 + pa_hi) * 8 + t4) * 136;
            const uint32_t* bal = bah + 8 * 136;
            const uint32_t* bbh = bufw + ((size_t)(cur * 8 + pb_hi) * 8 + t4) * 136;
            const uint32_t* bbl = bbh + 8 * 136;
#pragma unroll
            for (int nt = 0; nt < 16; ++nt) {
                const int n = nt * 8 + g;
                uint32_t b0, b1;
                b0 = bah[n]; b1 = bah[4 * 136 + n];
                MMA_BF16(acc[nt], fah[0], fah[1], fah[2], fah[3], b0, b1);
                MMA_BF16(acc[nt], fal[0], fal[1], fal[2], fal[3], b0, b1);
                b0 = bal[n]; b1 = bal[4 * 136 + n];
                MMA_BF16(acc[nt], fah[0], fah[1], fah[2], fah[3], b0, b1);
                b0 = bbh[n]; b1 = bbh[4 * 136 + n];
                MMA_BF16(acc[nt], fbh[0], fbh[1], fbh[2], fbh[3], b0, b1);
                MMA_BF16(acc[nt], fbl[0], fbl[1], fbl[2], fbl[3], b0, b1);
                b0 = bbl[n]; b1 = bbl[4 * 136 + n];
                MMA_BF16(acc[nt], fbh[0], fbh[1], fbh[2], fbh[3], b0, b1);
            }

            // ---- stage next weights ----
            if (u + 1 < M) {
                stw(cur ^ 1);
                if (u + 2 < M) ldw(u + 2, v0w);
            }
        }
    }

    // epilogue
    float* op = (out == 0) ? ts : tv + (size_t)(out - 1) * PLANE;
#pragma unroll
    for (int nt = 0; nt < 16; ++nt) {
        const int col = nt * 8 + 2 * t4;
        *(float2*)(op + (size_t)gb0 * 128 + col) =
            make_float2(cscale * acc[nt][0], cscale * acc[nt][1]);
        *(float2*)(op + (size_t)gb1 * 128 + col) =
            make_float2(cscale * acc[nt][2], cscale * acc[nt][3]);
    }
}

// ---------------------------------------------------------------------------
// split / pack / gemm / gate
// ---------------------------------------------------------------------------
__global__ void split_kernel(const float* __restrict__ x,
                             float* __restrict__ s, float* __restrict__ v) {
    int i = blockIdx.x * 256 + threadIdx.x;
    if (i >= BATCH * 64) return;
    int b = i >> 6, u = i & 63;
    const float* xr = x + b * 256;
    s[i] = xr[u];
    v[0 * PLANE + i] = xr[64 + 3 * u + 0];
    v[1 * PLANE + i] = xr[64 + 3 * u + 1];
    v[2 * PLANE + i] = xr[64 + 3 * u + 2];
}

__global__ void pack_kernel(const float* __restrict__ s,
                            const float* __restrict__ v,
                            float* __restrict__ out) {
    int i = blockIdx.x * 256 + threadIdx.x;
    if (i >= BATCH * 64) return;
    int b = i >> 6, u = i & 63;
    float* orow = out + b * 256;
    orow[u] = s[i];
    orow[64 + 3 * u + 0] = v[0 * PLANE + i];
    orow[64 + 3 * u + 1] = v[1 * PLANE + i];
    orow[64 + 3 * u + 2] = v[2 * PLANE + i];
}

template <int NC>
__global__ __launch_bounds__(256)
void gemm_kernel(const float* __restrict__ X, const float* __restrict__ Wm,
                 float* __restrict__ Y, int K, float scale) {
    constexpr int N = 32 * NC;
    X += (size_t)blockIdx.y * PLANE;
    Y += (size_t)blockIdx.y * PLANE;
    __shared__ float Xs[64][33];
    __shared__ float Ws[32][N + 1];
    const int tx = threadIdx.x, ty = threadIdx.y;
    const int tid = ty * 32 + tx;
    const int row0 = blockIdx.x * 64;

    float acc[8][NC];
#pragma unroll
    for (int r = 0; r < 8; ++r)
#pragma unroll
        for (int j = 0; j < NC; ++j) acc[r][j] = 0.f;

    for (int k0 = 0; k0 < K; k0 += 32) {
#pragma unroll
        for (int e = tid; e < 64 * 32; e += 256) {
            int r = e >> 5, kk = e & 31;
            Xs[r][kk] = X[(row0 + r) * K + k0 + kk];
        }
        for (int e = tid; e < 32 * N; e += 256) {
            int kk = e / N, n = e - kk * N;
            Ws[kk][n] = Wm[(k0 + kk) * N + n];
        }
        __syncthreads();
#pragma unroll 8
        for (int kk = 0; kk < 32; ++kk) {
            float wv[NC];
#pragma unroll
            for (int j = 0; j < NC; ++j) wv[j] = Ws[kk][tx * NC + j];
#pragma unroll
            for (int r = 0; r < 8; ++r) {
                float xv = Xs[ty * 8 + r][kk];
#pragma unroll
                for (int j = 0; j < NC; ++j) acc[r][j] += xv * wv[j];
            }
        }
        __syncthreads();
    }
#pragma unroll
    for (int r = 0; r < 8; ++r)
#pragma unroll
        for (int j = 0; j < NC; ++j)
            Y[(row0 + ty * 8 + r) * N + tx * NC + j] = scale * acc[r][j];
}

__global__ void gate_kernel(const float* __restrict__ sl, const float* __restrict__ g,
                            const float* __restrict__ vl,
                            float* __restrict__ gs, float* __restrict__ gv) {
    int i = blockIdx.x * 256 + threadIdx.x;
    if (i >= BATCH * 128) return;
    gs[i] = GAIN * tanhf(sl[i]);
    float t = GAIN * tanhf(g[i]);
    gv[0 * PLANE + i] = t * vl[0 * PLANE + i];
    gv[1 * PLANE + i] = t * vl[1 * PLANE + i];
    gv[2 * PLANE + i] = t * vl[2 * PLANE + i];
}

// ---------------------------------------------------------------------------
// Host orchestration
// ---------------------------------------------------------------------------
static inline void run_gemm(const float* X, const float* W, float* Y,
                            int K, int N, float scale, int planes) {
    dim3 blk(32, 8), grd(BATCH / 64, planes);
    if (N == 64) gemm_kernel<2><<<grd, blk>>>(X, W, Y, K, scale);
    else         gemm_kernel<4><<<grd, blk>>>(X, W, Y, K, scale);
}

extern "C" void kernel_launch(void* const* d_in, const int* in_sizes, int n_in,
                              void* d_out, int out_size) {
    const float* in[29];
    for (int i = 0; i < 29; ++i) in[i] = (const float*)d_in[i];
    float* out = (float*)d_out;

    float *s, *v, *s1, *v1, *s2, *v2, *ts, *tv;
    cudaGetSymbolAddress((void**)&s,  g_s);
    cudaGetSymbolAddress((void**)&v,  g_v);
    cudaGetSymbolAddress((void**)&s1, g_s1);
    cudaGetSymbolAddress((void**)&v1, g_v1);
    cudaGetSymbolAddress((void**)&s2, g_s2);
    cudaGetSymbolAddress((void**)&v2, g_v2);
    cudaGetSymbolAddress((void**)&ts, g_ts);
    cudaGetSymbolAddress((void**)&tv, g_tv);

    const int TP_SMEM = (2 * 8 * 8 * 136) * 4 + (4 * 64 * 17) * 4;  // 87040
    static bool attr_done = false;
    if (!attr_done) {
        cudaFuncSetAttribute(tp_mma_kernel<64>,
                             cudaFuncAttributeMaxDynamicSharedMemorySize, TP_SMEM);
        cudaFuncSetAttribute(tp_mma_kernel<128>,
                             cudaFuncAttributeMaxDynamicSharedMemorySize, TP_SMEM);
        attr_done = true;
    }

    const float c64  = 0.125f;
    const float c128 = 0.08838834764831845f;
    const float ctp1 = 1.0f / (64.0f  * 1.4142135623730951f);
    const float ctp2 = 1.0f / (128.0f * 1.4142135623730951f);

    split_kernel<<<BATCH * 64 / 256, 256>>>(in[0], s, v);

    // ---------------- block 1 (m = 64) ----------------
    run_gemm(s, in[1], s1, 64, 64, c64, 1);
    run_gemm(v, in[2], v1, 64, 64, c64, 3);
    run_gemm(s, in[3], s2, 64, 64, c64, 1);
    run_gemm(v, in[4], v2, 64, 64, c64, 3);

    tp_mma_kernel<64><<<BATCH / 64, 512, TP_SMEM>>>(
        s1, v1, s2, v2, in[5], in[6], in[7], in[8], ts, tv, ctp1);

    run_gemm(ts, in[9],  s1, 128, 128, c128, 1);
    run_gemm(ts, in[10], s2, 128, 128, c128, 1);
    run_gemm(tv, in[11], v1, 128, 128, c128, 3);
    gate_kernel<<<BATCH * 128 / 256, 256>>>(s1, s2, v1, ts, tv);

    run_gemm(ts, in[12], s, 128, 128, c128, 1);
    run_gemm(tv, in[13], v, 128, 128, c128, 3);

    // ---------------- block 2 (m = 128) ----------------
    run_gemm(s, in[14], s1, 128, 128, c128, 1);
    run_gemm(v, in[15], v1, 128, 128, c128, 3);
    run_gemm(s, in[16], s2, 128, 128, c128, 1);
    run_gemm(v, in[17], v2, 128, 128, c128, 3);

    tp_mma_kernel<128><<<BATCH / 64, 512, TP_SMEM>>>(
        s1, v1, s2, v2, in[18], in[19], in[20], in[21], ts, tv, ctp2);

    run_gemm(ts, in[22], s1, 128, 128, c128, 1);
    run_gemm(ts, in[23], s2, 128, 128, c128, 1);
    run_gemm(tv, in[24], v1, 128, 128, c128, 3);
    gate_kernel<<<BATCH * 128 / 256, 256>>>(s1, s2, v1, ts, tv);

    run_gemm(ts, in[25], s, 128, 128, c128, 1);
    run_gemm(tv, in[26], v, 128, 128, c128, 3);

    // ---------------- final linear + pack ----------------
    run_gemm(s, in[27], s1, 128, 64, c128, 1);
    run_gemm(v, in[28], v1, 128, 64, c128, 3);

    pack_kernel<<<BATCH * 64 / 256, 256>>>(s1, v1, out);
}